// round 1
// baseline (speedup 1.0000x reference)
#include <cuda_runtime.h>
#include <math.h>

// ---------------------------------------------------------------------------
// MinkUNet block on GB300: dense multi-kernel fp32 pipeline with packed
// f32x2 FMA, BN folded into consumers, deterministic 2-stage BN reductions.
// ---------------------------------------------------------------------------

#define NCAP 100352          // max voxels (actual N = 100000)
#define MCAP 65536           // max coarse voxels (B * (G/2)^3 = 65536)
#define NBSTAT 296           // fixed block count for stats partials

typedef unsigned long long ull;
struct U2 { ull a, b; };     // 16B = 4 floats, loaded via LDS.128/LDG.128

// ---------------- scratch (static device arrays; allocation-free) ----------
__device__ __align__(16) float g_h0[(size_t)NCAP * 32];
__device__ __align__(16) float g_p [(size_t)NCAP * 16];
__device__ __align__(16) float g_hds[(size_t)NCAP * 64];
__device__ __align__(16) float g_r [((size_t)NCAP + 1) * 16];   // pad row at N
__device__ __align__(16) float g_q [(size_t)NCAP * 16];
__device__ __align__(16) float g_z [(size_t)NCAP * 64];
__device__ __align__(16) float g_h2[((size_t)NCAP + 1) * 64];   // pad row at N
__device__ __align__(16) float g_outraw[(size_t)MCAP * 64];
__device__ float g_part[NBSTAT * 128];   // [block][sum(64) | sumsq(64)]
__device__ float g_tvec[8 * 32];
__device__ float g_sc0[32],  g_sh0[32];
__device__ float g_scP[16],  g_shP[16];
__device__ float g_scDS[64], g_shDS[64];
__device__ float g_scQ[16],  g_shQ[16];
__device__ float g_scZ[64],  g_shZ[64];
__device__ float g_scO[64],  g_shO[64];

// ---------------- f32x2 helpers --------------------------------------------
__device__ __forceinline__ ull packdup(float v) {
    ull r; asm("mov.b64 %0, {%1, %1};" : "=l"(r) : "f"(v)); return r;
}
__device__ __forceinline__ void fma2(ull& d, ull a, ull b) {
    asm("fma.rn.f32x2 %0, %1, %2, %0;" : "+l"(d) : "l"(a), "l"(b));
}

// ---------------- time MLP (tiny) ------------------------------------------
__global__ void k_time(const float* __restrict__ emb, const int* __restrict__ tim,
                       const float* __restrict__ Wt1, const float* __restrict__ bt1,
                       const float* __restrict__ Wt2, const float* __restrict__ bt2) {
    int b = blockIdx.x;
    int c = threadIdx.x;                    // 32 threads
    __shared__ float e[32], s[32];
    e[c] = emb[(size_t)tim[b] * 32 + c];
    __syncthreads();
    float u = bt1[c];
    #pragma unroll
    for (int j = 0; j < 32; j++) u = fmaf(e[j], Wt1[j * 32 + c], u);
    s[c] = u / (1.0f + expf(-u));           // silu
    __syncthreads();
    float v = bt2[c];
    #pragma unroll
    for (int j = 0; j < 32; j++) v = fmaf(s[j], Wt2[j * 32 + c], v);
    g_tvec[b * 32 + c] = v;
}

// ---------------- conv5: h0 = sparse_conv(x, nb5, W0)  [N,32] --------------
__global__ void __launch_bounds__(256, 1)
k_conv5(const float* __restrict__ x, const float* __restrict__ W0,
        const int* __restrict__ nb5, int N) {
    extern __shared__ float sW[];           // 125*8*32 = 32000 floats (128 KB)
    for (int t = threadIdx.x; t < 32000; t += 256) sW[t] = W0[t];
    __syncthreads();
    int tot = gridDim.x * 256;
    for (int i0 = blockIdx.x * 256 + threadIdx.x; i0 < N; i0 += 2 * tot) {
        int i1 = i0 + tot;
        bool h1 = i1 < N;
        ull a0[16], a1[16];
        #pragma unroll
        for (int c = 0; c < 16; c++) { a0[c] = 0ull; a1[c] = 0ull; }
        #pragma unroll 2
        for (int k = 0; k < 125; k++) {
            int ia = nb5[(size_t)k * N + i0];
            int ib = h1 ? nb5[(size_t)k * N + i1] : N;
            float4 z4 = make_float4(0.f, 0.f, 0.f, 0.f);
            float4 xa0 = z4, xa1 = z4, xb0 = z4, xb1 = z4;
            if (ia < N) { const float4* p = (const float4*)(x + (size_t)ia * 8); xa0 = p[0]; xa1 = p[1]; }
            if (ib < N) { const float4* p = (const float4*)(x + (size_t)ib * 8); xb0 = p[0]; xb1 = p[1]; }
            float fa[8] = {xa0.x, xa0.y, xa0.z, xa0.w, xa1.x, xa1.y, xa1.z, xa1.w};
            float fb[8] = {xb0.x, xb0.y, xb0.z, xb0.w, xb1.x, xb1.y, xb1.z, xb1.w};
            const U2* Wk = (const U2*)(sW + k * 256);
            #pragma unroll
            for (int j = 0; j < 8; j++) {
                ull pa = packdup(fa[j]), pb = packdup(fb[j]);
                #pragma unroll
                for (int c4 = 0; c4 < 8; c4++) {
                    U2 w = Wk[j * 8 + c4];
                    fma2(a0[2 * c4], pa, w.a); fma2(a0[2 * c4 + 1], pa, w.b);
                    fma2(a1[2 * c4], pb, w.a); fma2(a1[2 * c4 + 1], pb, w.b);
                }
            }
        }
        ull* o0 = (ull*)(g_h0 + (size_t)i0 * 32);
        #pragma unroll
        for (int c = 0; c < 16; c++) o0[c] = a0[c];
        if (h1) {
            ull* o1 = (ull*)(g_h0 + (size_t)i1 * 32);
            #pragma unroll
            for (int c = 0; c < 16; c++) o1[c] = a1[c];
        }
    }
}

// ---------------- column stats (deterministic, 2-stage) --------------------
__device__ const float* pick_buf(int w) {
    switch (w) {
        case 0: return g_h0;
        case 1: return g_p;
        case 2: return g_hds;
        case 3: return g_q;
        case 4: return g_z;
        default: return g_outraw;
    }
}

__global__ void k_colstats(int which, int R, int C) {
    const float* __restrict__ X = pick_buf(which);
    __shared__ float ss[256], sq[256];
    int c   = threadIdx.x % C;
    int rg  = threadIdx.x / C;
    int rpb = 256 / C;
    float s = 0.f, s2 = 0.f;
    for (int r = blockIdx.x * rpb + rg; r < R; r += gridDim.x * rpb) {
        float v = X[(size_t)r * C + c];
        s += v; s2 += v * v;
    }
    ss[threadIdx.x] = s; sq[threadIdx.x] = s2;
    __syncthreads();
    for (int off = 128; off >= C; off >>= 1) {
        if (threadIdx.x < off) {
            ss[threadIdx.x] += ss[threadIdx.x + off];
            sq[threadIdx.x] += sq[threadIdx.x + off];
        }
        __syncthreads();
    }
    if (threadIdx.x < C) {
        g_part[blockIdx.x * 128 + threadIdx.x]      = ss[threadIdx.x];
        g_part[blockIdx.x * 128 + 64 + threadIdx.x] = sq[threadIdx.x];
    }
}

__global__ void k_bnfinal(int which, int C, int R,
                          const float* __restrict__ g, const float* __restrict__ b) {
    int c = threadIdx.x;
    if (c >= C) return;
    float* sc; float* sh;
    switch (which) {
        case 0: sc = g_sc0;  sh = g_sh0;  break;
        case 1: sc = g_scP;  sh = g_shP;  break;
        case 2: sc = g_scDS; sh = g_shDS; break;
        case 3: sc = g_scQ;  sh = g_shQ;  break;
        case 4: sc = g_scZ;  sh = g_shZ;  break;
        default: sc = g_scO; sh = g_shO;  break;
    }
    float s = 0.f, s2 = 0.f;
    for (int i = 0; i < NBSTAT; i++) {
        s  += g_part[i * 128 + c];
        s2 += g_part[i * 128 + 64 + c];
    }
    float Rf = (float)R;
    float m  = s / Rf;
    float v  = s2 / Rf - m * m;
    float rs = rsqrtf(v + 1e-5f);
    float scale = g[c] * rs;
    sc[c] = scale;
    sh[c] = b[c] - m * scale;
}

// ---- fuse1: h = [relu(bn(h0)), t[bidx]]; p = h@Wb1; hds = h@Wds -----------
__global__ void __launch_bounds__(256)
k_fuse1(const float* __restrict__ Wb1, const float* __restrict__ Wds,
        const int* __restrict__ bidx, int N) {
    __shared__ __align__(16) float sWb1[64 * 16];
    __shared__ __align__(16) float sWds[64 * 64];
    __shared__ float sTv[256], ssc[32], ssh[32];
    for (int t = threadIdx.x; t < 1024; t += 256) sWb1[t] = Wb1[t];
    for (int t = threadIdx.x; t < 4096; t += 256) sWds[t] = Wds[t];
    if (threadIdx.x < 256) sTv[threadIdx.x] = g_tvec[threadIdx.x];
    if (threadIdx.x < 32) { ssc[threadIdx.x] = g_sc0[threadIdx.x]; ssh[threadIdx.x] = g_sh0[threadIdx.x]; }
    __syncthreads();
    int tot = gridDim.x * 256;
    for (int i = blockIdx.x * 256 + threadIdx.x; i < N; i += tot) {
        float hv[64];
        const float4* h0p = (const float4*)(g_h0 + (size_t)i * 32);
        #pragma unroll
        for (int q4 = 0; q4 < 8; q4++) {
            float4 v = h0p[q4];
            hv[4*q4+0] = fmaxf(fmaf(v.x, ssc[4*q4+0], ssh[4*q4+0]), 0.f);
            hv[4*q4+1] = fmaxf(fmaf(v.y, ssc[4*q4+1], ssh[4*q4+1]), 0.f);
            hv[4*q4+2] = fmaxf(fmaf(v.z, ssc[4*q4+2], ssh[4*q4+2]), 0.f);
            hv[4*q4+3] = fmaxf(fmaf(v.w, ssc[4*q4+3], ssh[4*q4+3]), 0.f);
        }
        int bb = bidx[i];
        #pragma unroll
        for (int j = 0; j < 32; j++) hv[32 + j] = sTv[bb * 32 + j];
        // p = h @ Wb1  (64 -> 16)
        ull ap[8];
        #pragma unroll
        for (int c = 0; c < 8; c++) ap[c] = 0ull;
        #pragma unroll 8
        for (int j = 0; j < 64; j++) {
            ull hj = packdup(hv[j]);
            const U2* w = (const U2*)(sWb1 + j * 16);
            #pragma unroll
            for (int c4 = 0; c4 < 4; c4++) {
                U2 ww = w[c4];
                fma2(ap[2*c4], hj, ww.a); fma2(ap[2*c4+1], hj, ww.b);
            }
        }
        ull* op = (ull*)(g_p + (size_t)i * 16);
        #pragma unroll
        for (int c = 0; c < 8; c++) op[c] = ap[c];
        // hds = h @ Wds (64 -> 64), two halves to bound registers
        #pragma unroll
        for (int hf = 0; hf < 2; hf++) {
            ull ah[16];
            #pragma unroll
            for (int c = 0; c < 16; c++) ah[c] = 0ull;
            #pragma unroll 4
            for (int j = 0; j < 64; j++) {
                ull hj = packdup(hv[j]);
                const U2* w = (const U2*)(sWds + j * 64 + hf * 32);
                #pragma unroll
                for (int c4 = 0; c4 < 8; c4++) {
                    U2 ww = w[c4];
                    fma2(ah[2*c4], hj, ww.a); fma2(ah[2*c4+1], hj, ww.b);
                }
            }
            ull* oh = (ull*)(g_hds + (size_t)i * 64 + hf * 32);
            #pragma unroll
            for (int c = 0; c < 16; c++) oh[c] = ah[c];
        }
    }
}

// ---- r = relu(bn(p)) with zero pad row ------------------------------------
__global__ void k_applyr(int N) {
    int tot = gridDim.x * blockDim.x;
    int elems = (N + 1) * 16;
    for (int t = blockIdx.x * blockDim.x + threadIdx.x; t < elems; t += tot) {
        int i = t >> 4, c = t & 15;
        float v = (i < N) ? fmaxf(fmaf(g_p[t], g_scP[c], g_shP[c]), 0.f) : 0.f;
        g_r[t] = v;
    }
}

// ---- conv3: q = sparse_conv(r, nb3, Wb2)  [N,16] --------------------------
__global__ void __launch_bounds__(256)
k_conv3(const float* __restrict__ Wb2, const int* __restrict__ nb3, int N) {
    __shared__ __align__(16) float sW[27 * 256];
    for (int t = threadIdx.x; t < 27 * 256; t += 256) sW[t] = Wb2[t];
    __syncthreads();
    int tot = gridDim.x * 256;
    for (int i0 = blockIdx.x * 256 + threadIdx.x; i0 < N; i0 += 2 * tot) {
        int i1 = i0 + tot;
        bool h1 = i1 < N;
        ull a0[8], a1[8];
        #pragma unroll
        for (int c = 0; c < 8; c++) { a0[c] = 0ull; a1[c] = 0ull; }
        #pragma unroll 3
        for (int k = 0; k < 27; k++) {
            int ia = nb3[(size_t)k * N + i0];
            int ib = h1 ? nb3[(size_t)k * N + i1] : N;
            const float4* ra = (const float4*)(g_r + (size_t)ia * 16);
            const float4* rb = (const float4*)(g_r + (size_t)ib * 16);
            float4 A0 = ra[0], A1 = ra[1], A2 = ra[2], A3 = ra[3];
            float4 B0 = rb[0], B1 = rb[1], B2 = rb[2], B3 = rb[3];
            float fa[16] = {A0.x,A0.y,A0.z,A0.w, A1.x,A1.y,A1.z,A1.w,
                            A2.x,A2.y,A2.z,A2.w, A3.x,A3.y,A3.z,A3.w};
            float fb[16] = {B0.x,B0.y,B0.z,B0.w, B1.x,B1.y,B1.z,B1.w,
                            B2.x,B2.y,B2.z,B2.w, B3.x,B3.y,B3.z,B3.w};
            const U2* Wk = (const U2*)(sW + k * 256);
            #pragma unroll
            for (int j = 0; j < 16; j++) {
                ull pa = packdup(fa[j]), pb = packdup(fb[j]);
                #pragma unroll
                for (int c4 = 0; c4 < 4; c4++) {
                    U2 w = Wk[j * 4 + c4];
                    fma2(a0[2*c4], pa, w.a); fma2(a0[2*c4+1], pa, w.b);
                    fma2(a1[2*c4], pb, w.a); fma2(a1[2*c4+1], pb, w.b);
                }
            }
        }
        ull* o0 = (ull*)(g_q + (size_t)i0 * 16);
        #pragma unroll
        for (int c = 0; c < 8; c++) o0[c] = a0[c];
        if (h1) {
            ull* o1 = (ull*)(g_q + (size_t)i1 * 16);
            #pragma unroll
            for (int c = 0; c < 8; c++) o1[c] = a1[c];
        }
    }
}

// ---- z = relu(bn(q)) @ Wb3  (16 -> 64) ------------------------------------
__global__ void __launch_bounds__(256)
k_gemmz(const float* __restrict__ Wb3, int N) {
    __shared__ __align__(16) float sW[16 * 64];
    __shared__ float ssc[16], ssh[16];
    for (int t = threadIdx.x; t < 1024; t += 256) sW[t] = Wb3[t];
    if (threadIdx.x < 16) { ssc[threadIdx.x] = g_scQ[threadIdx.x]; ssh[threadIdx.x] = g_shQ[threadIdx.x]; }
    __syncthreads();
    int tot = gridDim.x * 256;
    for (int i = blockIdx.x * 256 + threadIdx.x; i < N; i += tot) {
        const float4* qp = (const float4*)(g_q + (size_t)i * 16);
        float4 Q0 = qp[0], Q1 = qp[1], Q2 = qp[2], Q3 = qp[3];
        float qv[16] = {Q0.x,Q0.y,Q0.z,Q0.w, Q1.x,Q1.y,Q1.z,Q1.w,
                        Q2.x,Q2.y,Q2.z,Q2.w, Q3.x,Q3.y,Q3.z,Q3.w};
        float rr[16];
        #pragma unroll
        for (int j = 0; j < 16; j++) rr[j] = fmaxf(fmaf(qv[j], ssc[j], ssh[j]), 0.f);
        ull acc[32];
        #pragma unroll
        for (int c = 0; c < 32; c++) acc[c] = 0ull;
        #pragma unroll
        for (int j = 0; j < 16; j++) {
            ull pj = packdup(rr[j]);
            const U2* w = (const U2*)(sW + j * 64);
            #pragma unroll
            for (int c4 = 0; c4 < 16; c4++) {
                U2 ww = w[c4];
                fma2(acc[2*c4], pj, ww.a); fma2(acc[2*c4+1], pj, ww.b);
            }
        }
        ull* o = (ull*)(g_z + (size_t)i * 64);
        #pragma unroll
        for (int c = 0; c < 32; c++) o[c] = acc[c];
    }
}

// ---- h2 = relu(bn(z) + bn(hds)) with zero pad row -------------------------
__global__ void k_applyh2(int N) {
    int tot = gridDim.x * blockDim.x;
    int elems = (N + 1) * 64;
    for (int t = blockIdx.x * blockDim.x + threadIdx.x; t < elems; t += tot) {
        int i = t >> 6, c = t & 63;
        float v = 0.f;
        if (i < N) {
            float a = fmaf(g_z[t],   g_scZ[c],  g_shZ[c]);
            float b = fmaf(g_hds[t], g_scDS[c], g_shDS[c]);
            v = fmaxf(a + b, 0.f);
        }
        g_h2[t] = v;
    }
}

// ---- conv2: outraw = sparse_conv(h2, nb2, Wd)  [M,64] ---------------------
__global__ void __launch_bounds__(256, 1)
k_conv2k(const float* __restrict__ Wd, const int* __restrict__ nb2, int M) {
    extern __shared__ float sW2[];          // 8*64*64 = 32768 floats (128 KB)
    for (int t = threadIdx.x; t < 32768; t += 256) sW2[t] = Wd[t];
    __syncthreads();
    int tot = gridDim.x * 256;
    for (int m = blockIdx.x * 256 + threadIdx.x; m < M; m += tot) {
        ull acc[32];
        #pragma unroll
        for (int c = 0; c < 32; c++) acc[c] = 0ull;
        for (int k = 0; k < 8; k++) {
            int idx = nb2[(size_t)k * M + m];
            const float4* rp = (const float4*)(g_h2 + (size_t)idx * 64);
            #pragma unroll 4
            for (int j4 = 0; j4 < 16; j4++) {
                float4 v = rp[j4];
                float cm[4] = {v.x, v.y, v.z, v.w};
                #pragma unroll
                for (int jj = 0; jj < 4; jj++) {
                    ull pj = packdup(cm[jj]);
                    const U2* w = (const U2*)(sW2 + (size_t)k * 4096 + (j4 * 4 + jj) * 64);
                    #pragma unroll
                    for (int c4 = 0; c4 < 16; c4++) {
                        U2 ww = w[c4];
                        fma2(acc[2*c4], pj, ww.a); fma2(acc[2*c4+1], pj, ww.b);
                    }
                }
            }
        }
        ull* o = (ull*)(g_outraw + (size_t)m * 64);
        #pragma unroll
        for (int c = 0; c < 32; c++) o[c] = acc[c];
    }
}

// ---- out = relu(bn(outraw)) ------------------------------------------------
__global__ void k_out(float* __restrict__ out, int M) {
    int tot = gridDim.x * blockDim.x;
    int elems = M * 64;
    for (int t = blockIdx.x * blockDim.x + threadIdx.x; t < elems; t += tot) {
        int c = t & 63;
        out[t] = fmaxf(fmaf(g_outraw[t], g_scO[c], g_shO[c]), 0.f);
    }
}

// ---------------------------------------------------------------------------
extern "C" void kernel_launch(void* const* d_in, const int* in_sizes, int n_in,
                              void* d_out, int out_size) {
    const float* x    = (const float*)d_in[0];
    const float* W0   = (const float*)d_in[1];
    const float* g0   = (const float*)d_in[2];
    const float* b0   = (const float*)d_in[3];
    const float* emb  = (const float*)d_in[4];
    const float* Wt1  = (const float*)d_in[5];
    const float* bt1  = (const float*)d_in[6];
    const float* Wt2  = (const float*)d_in[7];
    const float* bt2  = (const float*)d_in[8];
    const float* Wb1  = (const float*)d_in[9];
    const float* gb1  = (const float*)d_in[10];
    const float* bb1  = (const float*)d_in[11];
    const float* Wb2  = (const float*)d_in[12];
    const float* gb2  = (const float*)d_in[13];
    const float* bb2  = (const float*)d_in[14];
    const float* Wb3  = (const float*)d_in[15];
    const float* gb3  = (const float*)d_in[16];
    const float* bb3  = (const float*)d_in[17];
    const float* Wds  = (const float*)d_in[18];
    const float* gds  = (const float*)d_in[19];
    const float* bds  = (const float*)d_in[20];
    const float* Wd   = (const float*)d_in[21];
    const float* gd   = (const float*)d_in[22];
    const float* bd   = (const float*)d_in[23];
    const int*   timei = (const int*)d_in[24];
    const int*   bidx  = (const int*)d_in[25];
    const int*   nb5   = (const int*)d_in[26];
    const int*   nb3   = (const int*)d_in[27];
    const int*   nb2   = (const int*)d_in[28];

    int N = in_sizes[0] / 8;
    int B = in_sizes[24];
    int M = in_sizes[28] / 8;
    if (N > NCAP) N = NCAP;
    if (M > MCAP) M = MCAP;

    cudaFuncSetAttribute(k_conv5,  cudaFuncAttributeMaxDynamicSharedMemorySize, 128000);
    cudaFuncSetAttribute(k_conv2k, cudaFuncAttributeMaxDynamicSharedMemorySize, 131072);

    int rowBlk  = (N + 255) / 256;

    // time MLP + init conv + BN0
    k_time<<<B, 32>>>(emb, timei, Wt1, bt1, Wt2, bt2);
    k_conv5<<<148, 256, 128000>>>(x, W0, nb5, N);
    k_colstats<<<NBSTAT, 256>>>(0, N, 32);
    k_bnfinal<<<1, 64>>>(0, 32, N, g0, b0);

    // concat+GEMMs (p, hds), their BN stats
    k_fuse1<<<rowBlk, 256>>>(Wb1, Wds, bidx, N);
    k_colstats<<<NBSTAT, 256>>>(1, N, 16);
    k_bnfinal<<<1, 64>>>(1, 16, N, gb1, bb1);
    k_colstats<<<NBSTAT, 256>>>(2, N, 64);
    k_bnfinal<<<1, 64>>>(2, 64, N, gds, bds);

    // r = relu(bn(p)) [+pad row]; conv3; BN(q)
    k_applyr<<<((N + 1) * 16 + 255) / 256, 256>>>(N);
    k_conv3<<<(N + 511) / 512, 256>>>(Wb2, nb3, N);
    k_colstats<<<NBSTAT, 256>>>(3, N, 16);
    k_bnfinal<<<1, 64>>>(3, 16, N, gb2, bb2);

    // z = relu(bn(q)) @ Wb3; BN(z)
    k_gemmz<<<rowBlk, 256>>>(Wb3, N);
    k_colstats<<<NBSTAT, 256>>>(4, N, 64);
    k_bnfinal<<<1, 64>>>(4, 64, N, gb3, bb3);

    // residual add -> h2 [+pad row]; final strided conv; BN(out); write out
    k_applyh2<<<((N + 1) * 64 + 255) / 256, 256>>>(N);
    k_conv2k<<<148, 256, 131072>>>(Wd, nb2, M);
    k_colstats<<<NBSTAT, 256>>>(5, M, 64);
    k_bnfinal<<<1, 64>>>(5, 64, M, gd, bd);
    k_out<<<(M * 64 + 255) / 256, 256>>>((float*)d_out, M);
}

// round 10
// speedup vs baseline: 1.2155x; 1.2155x over previous
#include <cuda_runtime.h>
#include <math.h>

// ---------------------------------------------------------------------------
// MinkUNet block on GB300, round 2 design (ninth submit; rounds 2-9 all hit
// GPU-acquisition timeouts, never measured):
//  - sparse convs warp-cooperative + valid-tap-compacted (ballot/ffs)
//  - voxel-major transposed neighbor tables (coalesced prefetch)
//  - f32x2 everywhere, weights packed as (even-j, odd-j) pairs in smem
//  - parallel BN finalize
// ---------------------------------------------------------------------------

#define NCAP 100352          // max voxels (actual N = 100000)
#define MCAP 65536           // max coarse voxels
#define NBSTAT 296           // stats partial blocks

typedef unsigned long long ull;

// ---------------- scratch (static device arrays; allocation-free) ----------
__device__ __align__(16) float g_h0[(size_t)NCAP * 32];
__device__ __align__(16) float g_p [(size_t)NCAP * 16];
__device__ __align__(16) float g_hds[(size_t)NCAP * 64];
__device__ __align__(16) float g_r [((size_t)NCAP + 1) * 16];   // pad row at N
__device__ __align__(16) float g_q [(size_t)NCAP * 16];
__device__ __align__(16) float g_z [(size_t)NCAP * 64];
__device__ __align__(16) float g_h2[((size_t)NCAP + 1) * 64];   // pad row at N
__device__ __align__(16) float g_outraw[(size_t)MCAP * 64];
__device__ int g_nb5T[(size_t)NCAP * 128];
__device__ int g_nb3T[(size_t)NCAP * 32];
__device__ int g_nb2T[(size_t)MCAP * 8];
__device__ float g_part[NBSTAT * 128];
__device__ float g_tvec[8 * 32];
__device__ float g_sc0[32],  g_sh0[32];
__device__ float g_scP[16],  g_shP[16];
__device__ float g_scDS[64], g_shDS[64];
__device__ float g_scQ[16],  g_shQ[16];
__device__ float g_scZ[64],  g_shZ[64];
__device__ float g_scO[64],  g_shO[64];

// ---------------- f32x2 helpers --------------------------------------------
__device__ __forceinline__ void fma2(ull& d, ull a, ull b) {
    asm("fma.rn.f32x2 %0, %1, %2, %0;" : "+l"(d) : "l"(a), "l"(b));
}
__device__ __forceinline__ ull pack2(float lo, float hi) {
    ull r; asm("mov.b64 %0, {%1, %2};" : "=l"(r) : "f"(lo), "f"(hi)); return r;
}
__device__ __forceinline__ float2 unpack2(ull v) {
    float2 f; asm("mov.b64 {%0, %1}, %2;" : "=f"(f.x), "=f"(f.y) : "l"(v)); return f;
}

// ---------------- transpose [K,Nc] -> [Nc,PAD] -----------------------------
__global__ void k_transpose(const int* __restrict__ src, int* __restrict__ dst,
                            int K, int Nc, int PAD) {
    __shared__ int tile[32][33];
    int i0 = blockIdx.x * 32, k0 = blockIdx.y * 32;
    for (int yy = threadIdx.y; yy < 32; yy += 8) {
        int k = k0 + yy, i = i0 + threadIdx.x;
        tile[yy][threadIdx.x] = (k < K && i < Nc) ? src[(size_t)k * Nc + i] : 0x7FFFFFFF;
    }
    __syncthreads();
    for (int yy = threadIdx.y; yy < 32; yy += 8) {
        int i = i0 + yy, k = k0 + threadIdx.x;
        if (i < Nc && k < PAD) dst[(size_t)i * PAD + k] = tile[threadIdx.x][yy];
    }
}

// ---------------- time MLP --------------------------------------------------
__global__ void k_time(const float* __restrict__ emb, const int* __restrict__ tim,
                       const float* __restrict__ Wt1, const float* __restrict__ bt1,
                       const float* __restrict__ Wt2, const float* __restrict__ bt2) {
    int b = blockIdx.x;
    int c = threadIdx.x;
    __shared__ float e[32], s[32];
    e[c] = emb[(size_t)tim[b] * 32 + c];
    __syncthreads();
    float u = bt1[c];
    #pragma unroll
    for (int j = 0; j < 32; j++) u = fmaf(e[j], Wt1[j * 32 + c], u);
    s[c] = u / (1.0f + expf(-u));
    __syncthreads();
    float v = bt2[c];
    #pragma unroll
    for (int j = 0; j < 32; j++) v = fmaf(s[j], Wt2[j * 32 + c], v);
    g_tvec[b * 32 + c] = v;
}

// ---------------- conv5: warp-pair compacted  [N,32] -----------------------
// Half-warp per voxel. Lane L15 owns channels L15 and L15+16.
// smem weights: ull[k][j2(4)][c(32)] = (W[k][2j2][c], W[k][2j2+1][c])
__global__ void __launch_bounds__(1024, 1)
k_conv5(const float* __restrict__ x, const float* __restrict__ W0, int N) {
    extern __shared__ ull sW[];                  // 125*128 = 16000 ull = 128000 B
    for (int u = threadIdx.x; u < 16000; u += 1024) {
        int k = u >> 7, r = u & 127, j2 = r >> 5, c = r & 31;
        sW[u] = pack2(W0[k * 256 + (2 * j2) * 32 + c],
                      W0[k * 256 + (2 * j2 + 1) * 32 + c]);
    }
    __syncthreads();
    int L   = threadIdx.x & 31;
    int L15 = L & 15;
    int half = L >> 4;
    int warp = (blockIdx.x * (blockDim.x >> 5)) + (threadIdx.x >> 5);
    int TW   = gridDim.x * (blockDim.x >> 5);
    int P    = (N + 1) >> 1;
    for (int p = warp; p < P; p += TW) {
        int iMine = 2 * p + half;
        bool live = iMine < N;
        const int* tp = g_nb5T + (size_t)(live ? iMine : 0) * 128;
        int ir[8]; unsigned um[8];
        #pragma unroll
        for (int b = 0; b < 8; b++) {
            int k = L15 + 16 * b;
            ir[b] = (live && k < 125) ? tp[k] : 0x7FFFFFFF;
        }
        #pragma unroll
        for (int b = 0; b < 8; b++) {
            unsigned vb = __ballot_sync(0xffffffffu, ir[b] < N);
            um[b] = (vb | (vb >> 16)) & 0xFFFFu;
        }
        ull a0 = 0, a1 = 0;
        #pragma unroll
        for (int b = 0; b < 8; b++) {
            unsigned m = um[b];
            while (m) {
                int kk = __ffs(m) - 1; m &= m - 1;
                int idx = __shfl_sync(0xffffffffu, ir[b], kk, 16);
                int k = 16 * b + kk;
                ull x0 = 0, x1 = 0, x2 = 0, x3 = 0;
                if (idx < N) {
                    const ulonglong2* xp = (const ulonglong2*)(x + (size_t)idx * 8);
                    ulonglong2 u0 = xp[0], u1 = xp[1];
                    x0 = u0.x; x1 = u0.y; x2 = u1.x; x3 = u1.y;
                }
                const ull* w = sW + k * 128 + L15;
                fma2(a0, x0, w[0]);   fma2(a1, x0, w[16]);
                fma2(a0, x1, w[32]);  fma2(a1, x1, w[48]);
                fma2(a0, x2, w[64]);  fma2(a1, x2, w[80]);
                fma2(a0, x3, w[96]);  fma2(a1, x3, w[112]);
            }
        }
        if (live) {
            float2 f0 = unpack2(a0), f1 = unpack2(a1);
            g_h0[(size_t)iMine * 32 + L15]      = f0.x + f0.y;
            g_h0[(size_t)iMine * 32 + L15 + 16] = f1.x + f1.y;
        }
    }
}

// ---------------- column stats (deterministic) -----------------------------
__device__ const float* pick_buf(int w) {
    switch (w) {
        case 0: return g_h0;
        case 1: return g_p;
        case 2: return g_hds;
        case 3: return g_q;
        case 4: return g_z;
        default: return g_outraw;
    }
}

__global__ void k_colstats(int which, int R, int C) {
    const float* __restrict__ X = pick_buf(which);
    __shared__ float ss[256], sq[256];
    int c   = threadIdx.x % C;
    int rg  = threadIdx.x / C;
    int rpb = 256 / C;
    float s = 0.f, s2 = 0.f;
    for (int r = blockIdx.x * rpb + rg; r < R; r += gridDim.x * rpb) {
        float v = X[(size_t)r * C + c];
        s += v; s2 += v * v;
    }
    ss[threadIdx.x] = s; sq[threadIdx.x] = s2;
    __syncthreads();
    for (int off = 128; off >= C; off >>= 1) {
        if (threadIdx.x < off) {
            ss[threadIdx.x] += ss[threadIdx.x + off];
            sq[threadIdx.x] += sq[threadIdx.x + off];
        }
        __syncthreads();
    }
    if (threadIdx.x < C) {
        g_part[blockIdx.x * 128 + threadIdx.x]      = ss[threadIdx.x];
        g_part[blockIdx.x * 128 + 64 + threadIdx.x] = sq[threadIdx.x];
    }
}

// ---------------- BN finalize: parallel ------------------------------------
__global__ void k_bnfinal(int which, int C, int R,
                          const float* __restrict__ g, const float* __restrict__ b) {
    __shared__ float S[1024], Q[1024];
    int t = threadIdx.x;
    int c = t & 63, grp = t >> 6;                 // 16 groups
    float s = 0.f, s2 = 0.f;
    for (int i = grp; i < NBSTAT; i += 16) {
        s  += g_part[i * 128 + c];
        s2 += g_part[i * 128 + 64 + c];
    }
    S[t] = s; Q[t] = s2;
    __syncthreads();
    for (int off = 512; off >= 64; off >>= 1) {
        if (t < off) { S[t] += S[t + off]; Q[t] += Q[t + off]; }
        __syncthreads();
    }
    if (t < C) {
        float* sc; float* sh;
        switch (which) {
            case 0: sc = g_sc0;  sh = g_sh0;  break;
            case 1: sc = g_scP;  sh = g_shP;  break;
            case 2: sc = g_scDS; sh = g_shDS; break;
            case 3: sc = g_scQ;  sh = g_shQ;  break;
            case 4: sc = g_scZ;  sh = g_shZ;  break;
            default: sc = g_scO; sh = g_shO;  break;
        }
        float Rf = (float)R;
        float m  = S[t] / Rf;
        float v  = Q[t] / Rf - m * m;
        float rs = rsqrtf(v + 1e-5f);
        float scale = g[t] * rs;
        sc[t] = scale;
        sh[t] = b[t] - m * scale;
    }
}

// ---- fuse1: h = [relu(bn(h0)), t[bidx]]; p = h@Wb1; hds = h@Wds -----------
__global__ void __launch_bounds__(256)
k_fuse1(const float* __restrict__ Wb1, const float* __restrict__ Wds,
        const int* __restrict__ bidx, int N) {
    __shared__ __align__(16) float sWb1[64 * 16];
    __shared__ __align__(16) float sWds[64 * 64];
    __shared__ float sTv[256], ssc[32], ssh[32];
    for (int t = threadIdx.x; t < 1024; t += 256) sWb1[t] = Wb1[t];
    for (int t = threadIdx.x; t < 4096; t += 256) sWds[t] = Wds[t];
    sTv[threadIdx.x] = g_tvec[threadIdx.x];
    if (threadIdx.x < 32) { ssc[threadIdx.x] = g_sc0[threadIdx.x]; ssh[threadIdx.x] = g_sh0[threadIdx.x]; }
    __syncthreads();
    int tot = gridDim.x * 256;
    for (int i = blockIdx.x * 256 + threadIdx.x; i < N; i += tot) {
        float hv[64];
        const float4* h0p = (const float4*)(g_h0 + (size_t)i * 32);
        #pragma unroll
        for (int q4 = 0; q4 < 8; q4++) {
            float4 v = h0p[q4];
            hv[4*q4+0] = fmaxf(fmaf(v.x, ssc[4*q4+0], ssh[4*q4+0]), 0.f);
            hv[4*q4+1] = fmaxf(fmaf(v.y, ssc[4*q4+1], ssh[4*q4+1]), 0.f);
            hv[4*q4+2] = fmaxf(fmaf(v.z, ssc[4*q4+2], ssh[4*q4+2]), 0.f);
            hv[4*q4+3] = fmaxf(fmaf(v.w, ssc[4*q4+3], ssh[4*q4+3]), 0.f);
        }
        int bb = bidx[i];
        #pragma unroll
        for (int j = 0; j < 32; j++) hv[32 + j] = sTv[bb * 32 + j];
        ull ap[8];
        #pragma unroll
        for (int c = 0; c < 8; c++) ap[c] = 0ull;
        #pragma unroll 8
        for (int j = 0; j < 64; j++) {
            ull hj = pack2(hv[j], hv[j]);
            const ull* w = (const ull*)(sWb1 + j * 16);
            #pragma unroll
            for (int c2 = 0; c2 < 8; c2++) fma2(ap[c2], hj, w[c2]);
        }
        ull* op = (ull*)(g_p + (size_t)i * 16);
        #pragma unroll
        for (int c = 0; c < 8; c++) op[c] = ap[c];
        #pragma unroll
        for (int hf = 0; hf < 2; hf++) {
            ull ah[16];
            #pragma unroll
            for (int c = 0; c < 16; c++) ah[c] = 0ull;
            #pragma unroll 4
            for (int j = 0; j < 64; j++) {
                ull hj = pack2(hv[j], hv[j]);
                const ull* w = (const ull*)(sWds + j * 64 + hf * 32);
                #pragma unroll
                for (int c2 = 0; c2 < 16; c2++) fma2(ah[c2], hj, w[c2]);
            }
            ull* oh = (ull*)(g_hds + (size_t)i * 64 + hf * 32);
            #pragma unroll
            for (int c = 0; c < 16; c++) oh[c] = ah[c];
        }
    }
}

// ---- r = relu(bn(p)) with zero pad row ------------------------------------
__global__ void k_applyr(int N) {
    int tot = gridDim.x * blockDim.x;
    int elems = (N + 1) * 16;
    for (int t = blockIdx.x * blockDim.x + threadIdx.x; t < elems; t += tot) {
        int i = t >> 4, c = t & 15;
        g_r[t] = (i < N) ? fmaxf(fmaf(g_p[t], g_scP[c], g_shP[c]), 0.f) : 0.f;
    }
}

// ---------------- conv3: warp-pair compacted  [N,16] -----------------------
__global__ void __launch_bounds__(1024, 2)
k_conv3(const float* __restrict__ Wb2, int N) {
    __shared__ ull sW3[27 * 128];                // 3456 ull = 27648 B
    for (int u = threadIdx.x; u < 3456; u += 1024) {
        int k = u >> 7, r = u & 127, j2 = r >> 4, c = r & 15;
        sW3[u] = pack2(Wb2[k * 256 + (2 * j2) * 16 + c],
                       Wb2[k * 256 + (2 * j2 + 1) * 16 + c]);
    }
    __syncthreads();
    int L   = threadIdx.x & 31;
    int L15 = L & 15;
    int half = L >> 4;
    int warp = (blockIdx.x * (blockDim.x >> 5)) + (threadIdx.x >> 5);
    int TW   = gridDim.x * (blockDim.x >> 5);
    int P    = (N + 1) >> 1;
    for (int p = warp; p < P; p += TW) {
        int iMine = 2 * p + half;
        bool live = iMine < N;
        const int* tp = g_nb3T + (size_t)(live ? iMine : 0) * 32;
        int ir[2]; unsigned um[2];
        #pragma unroll
        for (int b = 0; b < 2; b++) {
            int k = L15 + 16 * b;
            ir[b] = (live && k < 27) ? tp[k] : 0x7FFFFFFF;
        }
        #pragma unroll
        for (int b = 0; b < 2; b++) {
            unsigned vb = __ballot_sync(0xffffffffu, ir[b] < N);
            um[b] = (vb | (vb >> 16)) & 0xFFFFu;
        }
        ull a0 = 0, a1 = 0;
        #pragma unroll
        for (int b = 0; b < 2; b++) {
            unsigned m = um[b];
            while (m) {
                int kk = __ffs(m) - 1; m &= m - 1;
                int idxr = __shfl_sync(0xffffffffu, ir[b], kk, 16);
                int idx = (idxr < N) ? idxr : N;        // pad row (zeros)
                int k = 16 * b + kk;
                const ulonglong2* rp = (const ulonglong2*)(g_r + (size_t)idx * 16);
                ulonglong2 u0 = rp[0], u1 = rp[1], u2 = rp[2], u3 = rp[3];
                const ull* w = sW3 + k * 128 + L15;
                fma2(a0, u0.x, w[0]);   fma2(a1, u0.y, w[16]);
                fma2(a0, u1.x, w[32]);  fma2(a1, u1.y, w[48]);
                fma2(a0, u2.x, w[64]);  fma2(a1, u2.y, w[80]);
                fma2(a0, u3.x, w[96]);  fma2(a1, u3.y, w[112]);
            }
        }
        if (live) {
            float2 f0 = unpack2(a0), f1 = unpack2(a1);
            g_q[(size_t)iMine * 16 + L15] = f0.x + f0.y + f1.x + f1.y;
        }
    }
}

// ---- z = relu(bn(q)) @ Wb3  (16 -> 64) ------------------------------------
__global__ void __launch_bounds__(256)
k_gemmz(const float* __restrict__ Wb3, int N) {
    __shared__ __align__(16) float sW[16 * 64];
    __shared__ float ssc[16], ssh[16];
    for (int t = threadIdx.x; t < 1024; t += 256) sW[t] = Wb3[t];
    if (threadIdx.x < 16) { ssc[threadIdx.x] = g_scQ[threadIdx.x]; ssh[threadIdx.x] = g_shQ[threadIdx.x]; }
    __syncthreads();
    int tot = gridDim.x * 256;
    for (int i = blockIdx.x * 256 + threadIdx.x; i < N; i += tot) {
        const float4* qp = (const float4*)(g_q + (size_t)i * 16);
        float4 Q0 = qp[0], Q1 = qp[1], Q2 = qp[2], Q3 = qp[3];
        float qv[16] = {Q0.x,Q0.y,Q0.z,Q0.w, Q1.x,Q1.y,Q1.z,Q1.w,
                        Q2.x,Q2.y,Q2.z,Q2.w, Q3.x,Q3.y,Q3.z,Q3.w};
        float rr[16];
        #pragma unroll
        for (int j = 0; j < 16; j++) rr[j] = fmaxf(fmaf(qv[j], ssc[j], ssh[j]), 0.f);
        ull acc[32];
        #pragma unroll
        for (int c = 0; c < 32; c++) acc[c] = 0ull;
        #pragma unroll
        for (int j = 0; j < 16; j++) {
            ull pj = pack2(rr[j], rr[j]);
            const ull* w = (const ull*)(sW + j * 64);
            #pragma unroll
            for (int c2 = 0; c2 < 32; c2++) fma2(acc[c2], pj, w[c2]);
        }
        ull* o = (ull*)(g_z + (size_t)i * 64);
        #pragma unroll
        for (int c = 0; c < 32; c++) o[c] = acc[c];
    }
}

// ---- h2 = relu(bn(z) + bn(hds)) with zero pad row -------------------------
__global__ void k_applyh2(int N) {
    int tot = gridDim.x * blockDim.x;
    int elems = (N + 1) * 64;
    for (int t = blockIdx.x * blockDim.x + threadIdx.x; t < elems; t += tot) {
        int i = t >> 6, c = t & 63;
        float v = 0.f;
        if (i < N) {
            float a = fmaf(g_z[t],   g_scZ[c],  g_shZ[c]);
            float b = fmaf(g_hds[t], g_scDS[c], g_shDS[c]);
            v = fmaxf(a + b, 0.f);
        }
        g_h2[t] = v;
    }
}

// ---------------- conv2: warp-per-output compacted [M,64] ------------------
__global__ void __launch_bounds__(1024, 1)
k_conv2(const float* __restrict__ Wd, int M, int N) {
    extern __shared__ ull sW2[];                 // 8*2048 = 16384 ull = 131072 B
    for (int u = threadIdx.x; u < 16384; u += 1024) {
        int k = u >> 11, r = u & 2047, j2 = r >> 6, c = r & 63;
        sW2[u] = pack2(Wd[k * 4096 + (2 * j2) * 64 + c],
                       Wd[k * 4096 + (2 * j2 + 1) * 64 + c]);
    }
    __syncthreads();
    int L = threadIdx.x & 31;
    int warp = (blockIdx.x * (blockDim.x >> 5)) + (threadIdx.x >> 5);
    int TW   = gridDim.x * (blockDim.x >> 5);
    for (int mo = warp; mo < M; mo += TW) {
        int pk = (L < 8) ? g_nb2T[(size_t)mo * 8 + L] : 0x7FFFFFFF;
        unsigned vm = __ballot_sync(0xffffffffu, pk < N) & 0xFFu;
        ull a0 = 0, a1 = 0;
        while (vm) {
            int k = __ffs(vm) - 1; vm &= vm - 1;
            int idx = __shfl_sync(0xffffffffu, pk, k);
            const ulonglong2* hp = (const ulonglong2*)(g_h2 + (size_t)idx * 64);
            const ull* w = sW2 + k * 2048 + L;
            #pragma unroll
            for (int ch = 0; ch < 2; ch++) {
                ulonglong2 u0 = hp[ch*8+0], u1 = hp[ch*8+1], u2 = hp[ch*8+2], u3 = hp[ch*8+3];
                ulonglong2 u4 = hp[ch*8+4], u5 = hp[ch*8+5], u6 = hp[ch*8+6], u7 = hp[ch*8+7];
                const ull* wc = w + ch * 1024;
                fma2(a0, u0.x, wc[0*64]);   fma2(a1, u0.x, wc[0*64+32]);
                fma2(a0, u0.y, wc[1*64]);   fma2(a1, u0.y, wc[1*64+32]);
                fma2(a0, u1.x, wc[2*64]);   fma2(a1, u1.x, wc[2*64+32]);
                fma2(a0, u1.y, wc[3*64]);   fma2(a1, u1.y, wc[3*64+32]);
                fma2(a0, u2.x, wc[4*64]);   fma2(a1, u2.x, wc[4*64+32]);
                fma2(a0, u2.y, wc[5*64]);   fma2(a1, u2.y, wc[5*64+32]);
                fma2(a0, u3.x, wc[6*64]);   fma2(a1, u3.x, wc[6*64+32]);
                fma2(a0, u3.y, wc[7*64]);   fma2(a1, u3.y, wc[7*64+32]);
                fma2(a0, u4.x, wc[8*64]);   fma2(a1, u4.x, wc[8*64+32]);
                fma2(a0, u4.y, wc[9*64]);   fma2(a1, u4.y, wc[9*64+32]);
                fma2(a0, u5.x, wc[10*64]);  fma2(a1, u5.x, wc[10*64+32]);
                fma2(a0, u5.y, wc[11*64]);  fma2(a1, u5.y, wc[11*64+32]);
                fma2(a0, u6.x, wc[12*64]);  fma2(a1, u6.x, wc[12*64+32]);
                fma2(a0, u6.y, wc[13*64]);  fma2(a1, u6.y, wc[13*64+32]);
                fma2(a0, u7.x, wc[14*64]);  fma2(a1, u7.x, wc[14*64+32]);
                fma2(a0, u7.y, wc[15*64]);  fma2(a1, u7.y, wc[15*64+32]);
            }
        }
        float2 f0 = unpack2(a0), f1 = unpack2(a1);
        g_outraw[(size_t)mo * 64 + L]      = f0.x + f0.y;
        g_outraw[(size_t)mo * 64 + L + 32] = f1.x + f1.y;
    }
}

// ---- out = relu(bn(outraw)) -----------------------------------------------
__global__ void k_out(float* __restrict__ out, int M) {
    int tot = gridDim.x * blockDim.x;
    int elems = M * 64;
    for (int t = blockIdx.x * blockDim.x + threadIdx.x; t < elems; t += tot) {
        int c = t & 63;
        out[t] = fmaxf(fmaf(g_outraw[t], g_scO[c], g_shO[c]), 0.f);
    }
}

// ---------------------------------------------------------------------------
extern "C" void kernel_launch(void* const* d_in, const int* in_sizes, int n_in,
                              void* d_out, int out_size) {
    const float* x    = (const float*)d_in[0];
    const float* W0   = (const float*)d_in[1];
    const float* g0   = (const float*)d_in[2];
    const float* b0   = (const float*)d_in[3];
    const float* emb  = (const float*)d_in[4];
    const float* Wt1  = (const float*)d_in[5];
    const float* bt1  = (const float*)d_in[6];
    const float* Wt2  = (const float*)d_in[7];
    const float* bt2  = (const float*)d_in[8];
    const float* Wb1  = (const float*)d_in[9];
    const float* gb1  = (const float*)d_in[10];
    const float* bb1  = (const float*)d_in[11];
    const float* Wb2  = (const float*)d_in[12];
    const float* gb2  = (const float*)d_in[13];
    const float* bb2  = (const float*)d_in[14];
    const float* Wb3  = (const float*)d_in[15];
    const float* gb3  = (const float*)d_in[16];
    const float* bb3  = (const float*)d_in[17];
    const float* Wds  = (const float*)d_in[18];
    const float* gds  = (const float*)d_in[19];
    const float* bds  = (const float*)d_in[20];
    const float* Wd   = (const float*)d_in[21];
    const float* gd   = (const float*)d_in[22];
    const float* bd   = (const float*)d_in[23];
    const int*   timei = (const int*)d_in[24];
    const int*   bidx  = (const int*)d_in[25];
    const int*   nb5   = (const int*)d_in[26];
    const int*   nb3   = (const int*)d_in[27];
    const int*   nb2   = (const int*)d_in[28];

    int N = in_sizes[0] / 8;
    int B = in_sizes[24];
    int M = in_sizes[28] / 8;
    if (N > NCAP) N = NCAP;
    if (M > MCAP) M = MCAP;

    cudaFuncSetAttribute(k_conv5, cudaFuncAttributeMaxDynamicSharedMemorySize, 128000);
    cudaFuncSetAttribute(k_conv2, cudaFuncAttributeMaxDynamicSharedMemorySize, 131072);

    int* nb5T; cudaGetSymbolAddress((void**)&nb5T, g_nb5T);
    int* nb3T; cudaGetSymbolAddress((void**)&nb3T, g_nb3T);
    int* nb2T; cudaGetSymbolAddress((void**)&nb2T, g_nb2T);

    dim3 tb(32, 8);
    k_transpose<<<dim3((N + 31) / 32, 4), tb>>>(nb5, nb5T, 125, N, 128);
    k_transpose<<<dim3((N + 31) / 32, 1), tb>>>(nb3, nb3T, 27, N, 32);
    k_transpose<<<dim3((M + 31) / 32, 1), tb>>>(nb2, nb2T, 8, M, 8);

    int rowBlk = (N + 255) / 256;

    k_time<<<B, 32>>>(emb, timei, Wt1, bt1, Wt2, bt2);
    k_conv5<<<148, 1024, 128000>>>(x, W0, N);
    k_colstats<<<NBSTAT, 256>>>(0, N, 32);
    k_bnfinal<<<1, 1024>>>(0, 32, N, g0, b0);

    k_fuse1<<<rowBlk, 256>>>(Wb1, Wds, bidx, N);
    k_colstats<<<NBSTAT, 256>>>(1, N, 16);
    k_bnfinal<<<1, 1024>>>(1, 16, N, gb1, bb1);
    k_colstats<<<NBSTAT, 256>>>(2, N, 64);
    k_bnfinal<<<1, 1024>>>(2, 64, N, gds, bds);

    k_applyr<<<((N + 1) * 16 + 255) / 256, 256>>>(N);
    k_conv3<<<296, 1024>>>(Wb2, N);
    k_colstats<<<NBSTAT, 256>>>(3, N, 16);
    k_bnfinal<<<1, 1024>>>(3, 16, N, gb2, bb2);

    k_gemmz<<<rowBlk, 256>>>(Wb3, N);
    k_colstats<<<NBSTAT, 256>>>(4, N, 64);
    k_bnfinal<<<1, 1024>>>(4, 64, N, gb3, bb3);

    k_applyh2<<<((N + 1) * 64 + 255) / 256, 256>>>(N);
    k_conv2<<<148, 1024, 131072>>>(Wd, M, N);
    k_colstats<<<NBSTAT, 256>>>(5, M, 64);
    k_bnfinal<<<1, 1024>>>(5, 64, M, gd, bd);
    k_out<<<(M * 64 + 255) / 256, 256>>>((float*)d_out, M);
}